// round 4
// baseline (speedup 1.0000x reference)
#include <cuda_runtime.h>
#include <cstdint>
#include <cstddef>

typedef unsigned long long ull;

#define Tlen   512
#define NB     4096
#define NTHR   224          // 7 warps: 200 tasks + fc + x-stager + 22 spare
#define NTICKS (Tlen + 4)   // diagonal pipeline: layer l does t=T-l; fc does t=T-4

__device__ __forceinline__ ull pack2(float lo, float hi) {
    return (ull)__float_as_uint(lo) | ((ull)__float_as_uint(hi) << 32);
}
__device__ __forceinline__ float hsum2(ull v) {
    float lo = __uint_as_float((unsigned)v);
    float hi = __uint_as_float((unsigned)(v >> 32));
    return lo + hi;
}
__device__ __forceinline__ void fma2(ull& acc, ull a, ull b) {
    asm("fma.rn.f32x2 %0, %1, %2, %0;" : "+l"(acc) : "l"(a), "l"(b));
}
__device__ __forceinline__ float fast_sig(float x) {
    float e, r;
    asm("ex2.approx.ftz.f32 %0, %1;" : "=f"(e) : "f"(x * -1.4426950408889634f));
    asm("rcp.approx.ftz.f32 %0, %1;" : "=f"(r) : "f"(e + 1.0f));
    return r;
}
__device__ __forceinline__ float fast_tanh(float x) {
    return fmaf(2.0f, fast_sig(2.0f * x), -1.0f);
}

// v rows (per layer, double buffered), 52 floats each:
//   l=0   : [ x_t, h0_self(25), 0 x 26 ]
//   l=1..3: [ h_{l-1}(25), 0, h_l_self(25), 0 ]
// fc reads v[3] with weights only on [26..50].

__global__ void __launch_bounds__(NTHR, 2) lstm_kernel(
    const float* __restrict__ x,
    const float* __restrict__ Wih1, const float* __restrict__ Whh1,
    const float* __restrict__ bih1, const float* __restrict__ bhh1,
    const float* __restrict__ Wih2, const float* __restrict__ Whh2,
    const float* __restrict__ bih2, const float* __restrict__ bhh2,
    const float* __restrict__ Wih3, const float* __restrict__ Whh3,
    const float* __restrict__ bih3, const float* __restrict__ bhh3,
    const float* __restrict__ Wih4, const float* __restrict__ Whh4,
    const float* __restrict__ bih4, const float* __restrict__ bhh4,
    const float* __restrict__ Wfc, const float* __restrict__ bfc,
    float* __restrict__ out, int write_states)
{
    __shared__ __align__(16) float v[4][2][52];

    const int tid = threadIdx.x;
    const int gb  = blockIdx.x;          // one batch element per block

    // ---- role decode ----
    const bool isTask   = tid < 200;
    const bool isFc     = (tid == 200);
    const bool isStager = (tid == 201);
    int l, u, p;
    if (isTask) { l = tid / 50; int r = tid - l * 50; u = r >> 1; p = r & 1; }
    else        { l = 3; u = 0; p = tid & 1; }

    // ---- zero v buffers ----
    for (int i = tid; i < 4 * 2 * 52; i += NTHR) ((float*)v)[i] = 0.f;

    // ---- load this thread's 2 gate rows into registers (fused 52-wide) ----
    ull W0x[13], W0y[13], W1x[13], W1y[13];
    float bias0 = 0.f, bias1 = 0.f;
    {
        const float* WihL[4] = {Wih1, Wih2, Wih3, Wih4};
        const float* WhhL[4] = {Whh1, Whh2, Whh3, Whh4};
        const float* bihL[4] = {bih1, bih2, bih3, bih4};
        const float* bhhL[4] = {bhh1, bhh2, bhh3, bhh4};

        const float* pa0 = Wih1; const float* pb0 = Wih1;
        const float* pa1 = Wih1; const float* pb1 = Wih1;
        int aLo = 1, aHi = 0, bLo = 1, bHi = 0;   // empty by default

        if (isTask) {
            // gate order (i,f,g,o): p=0 -> rows {u, 25+u}; p=1 -> {50+u, 75+u}
            int row0 = p * 50 + u;
            int row1 = row0 + 25;
            if (l == 0) {
                pa0 = Wih1 + row0;        pa1 = Wih1 + row1;
                aLo = 0; aHi = 1;
                pb0 = Whh1 + row0 * 25;   pb1 = Whh1 + row1 * 25;
                bLo = 1; bHi = 26;
            } else {
                pa0 = WihL[l] + row0 * 25; pa1 = WihL[l] + row1 * 25;
                aLo = 0; aHi = 25;
                pb0 = WhhL[l] + row0 * 25; pb1 = WhhL[l] + row1 * 25;
                bLo = 26; bHi = 51;
            }
            bias0 = bihL[l][row0] + bhhL[l][row0];
            bias1 = bihL[l][row1] + bhhL[l][row1];
        } else if (isFc) {
            pb0 = Wfc; bLo = 26; bHi = 51;   // dot with h3 slot of v[3]
            bias0 = bfc[0];
        }

#pragma unroll
        for (int ch = 0; ch < 13; ++ch) {
            float f0[4], f1[4];
#pragma unroll
            for (int j = 0; j < 4; ++j) {
                int k = ch * 4 + j;
                float a = 0.f, b = 0.f;
                if (k >= aLo && k < aHi) { a = pa0[k - aLo]; b = pa1[k - aLo]; }
                if (k >= bLo && k < bHi) { a = pb0[k - bLo]; b = pb1[k - bLo]; }
                f0[j] = a; f1[j] = b;
            }
            W0x[ch] = pack2(f0[0], f0[1]); W0y[ch] = pack2(f0[2], f0[3]);
            W1x[ch] = pack2(f1[0], f1[1]); W1y[ch] = pack2(f1[2], f1[3]);
        }
    }

    // ---- stage x(0), prefetch x(1) ----
    float xreg = 0.f;
    if (isStager) {
        v[0][0][0] = x[gb];
        xreg = x[(size_t)NB + gb];
    }
    __syncthreads();

    float c = 0.f, h = 0.f;
    const float kmul = p ? 2.f : 1.f;     // tanh via 2*sig(2x)-1 on odd lanes
    const float kadd = p ? -1.f : 0.f;
    int par = l & 1;                      // = (T + l) & 1 == (T - l) & 1
    const int selfIdx = (l == 0) ? (1 + u) : (26 + u);

    for (int T = 0; T < NTICKS; ++T) {
        // ---- dual-gate dot product over the 52-float v row (broadcast LDS) ----
        ull A0 = pack2(bias0, 0.f), B0 = 0ull;
        ull A1 = pack2(bias1, 0.f), B1 = 0ull;
        const ulonglong2* V = (const ulonglong2*)v[l][par];
#pragma unroll
        for (int ch = 0; ch < 13; ++ch) {
            ulonglong2 hv = V[ch];
            fma2(A0, W0x[ch], hv.x); fma2(B0, W0y[ch], hv.y);
            fma2(A1, W1x[ch], hv.x); fma2(B1, W1y[ch], hv.y);
        }
        float s0 = hsum2(A0) + hsum2(B0);
        float s1 = hsum2(A1) + hsum2(B1);

        // ---- special roles (warp 6, non-divergent-exit) ----
        if (isFc) {
            int t = T - 4;                 // y(t) = h4(t)@Wfc + bfc
            if (t >= 0) out[(size_t)t * NB + gb] = s0;
        }
        if (isStager) {
            v[0][(T + 1) & 1][0] = xreg;   // x(T+1) for layer0's next tick
            int t2 = (T + 2 < Tlen) ? T + 2 : Tlen - 1;
            xreg = x[(size_t)t2 * NB + gb];
        }

        // ---- warp-uniform activations, then pair exchange ----
        float u0 = fast_sig(kmul * s0);
        float a0 = fmaf(kmul, u0, kadd);   // p=0: sig(s0)=sig(i|f-pre)  p=1: tanh(s0)
        float a1 = fast_sig(s1);           // p=0: sig(f)               p=1: sig(o)
        float x0 = __shfl_xor_sync(0xFFFFFFFFu, a0, 1);
        float x1 = __shfl_xor_sync(0xFFFFFFFFu, a1, 1);
        float si = p ? x0 : a0;
        float sf = p ? x1 : a1;
        float tg = p ? a0 : x0;
        float so = p ? a1 : x1;

        bool act = isTask && (T >= l) && (T - l < Tlen);
        if (act) {
            c = fmaf(sf, c, si * tg);      // both lanes keep identical c
            h = so * fast_tanh(c);
            if (p == 0)      v[l][par ^ 1][selfIdx] = h;   // own recurrence
            else if (l < 3)  v[l + 1][par][u]       = h;   // feed next layer
        }
        par ^= 1;
        __syncthreads();
    }

    // ---- final states (h1,c1,h2,c2,h3,c3,h4,c4), each [4096,25] ----
    if (write_states && isTask && p == 0) {
        size_t base = (size_t)Tlen * NB;
        const size_t S = (size_t)NB * 25;
        size_t idx = (size_t)gb * 25 + u;
        out[base + (size_t)(2 * l) * S + idx]     = h;
        out[base + (size_t)(2 * l + 1) * S + idx] = c;
    }
}

extern "C" void kernel_launch(void* const* d_in, const int* in_sizes, int n_in,
                              void* d_out, int out_size) {
    (void)n_in; (void)in_sizes;
    const float* x    = (const float*)d_in[0];
    const float* Wih1 = (const float*)d_in[1];
    const float* Whh1 = (const float*)d_in[2];
    const float* bih1 = (const float*)d_in[3];
    const float* bhh1 = (const float*)d_in[4];
    const float* Wih2 = (const float*)d_in[5];
    const float* Whh2 = (const float*)d_in[6];
    const float* bih2 = (const float*)d_in[7];
    const float* bhh2 = (const float*)d_in[8];
    const float* Wih3 = (const float*)d_in[9];
    const float* Whh3 = (const float*)d_in[10];
    const float* bih3 = (const float*)d_in[11];
    const float* bhh3 = (const float*)d_in[12];
    const float* Wih4 = (const float*)d_in[13];
    const float* Whh4 = (const float*)d_in[14];
    const float* bih4 = (const float*)d_in[15];
    const float* bhh4 = (const float*)d_in[16];
    const float* Wfc  = (const float*)d_in[17];
    const float* bfc  = (const float*)d_in[18];

    int write_states = (out_size >= Tlen * NB + 8 * NB * 25) ? 1 : 0;

    lstm_kernel<<<NB, NTHR>>>(
        x, Wih1, Whh1, bih1, bhh1,
        Wih2, Whh2, bih2, bhh2,
        Wih3, Whh3, bih3, bhh3,
        Wih4, Whh4, bih4, bhh4,
        Wfc, bfc, (float*)d_out, write_states);
}

// round 5
// speedup vs baseline: 1.2205x; 1.2205x over previous
#include <cuda_runtime.h>
#include <cstdint>
#include <cstddef>

typedef unsigned long long ull;

#define Tlen   512
#define NB     4096
#define BPB    2            // batch elements per block
#define NTHR   224          // 7 warps: 200 tasks + fc + stager + spares
#define NTICKS (Tlen + 4)   // diagonal pipeline: layer l does t=T-l; fc does t=T-4

__device__ __forceinline__ ull pack2(float lo, float hi) {
    return (ull)__float_as_uint(lo) | ((ull)__float_as_uint(hi) << 32);
}
__device__ __forceinline__ float hsum2(ull v) {
    float lo = __uint_as_float((unsigned)v);
    float hi = __uint_as_float((unsigned)(v >> 32));
    return lo + hi;
}
__device__ __forceinline__ void fma2(ull& acc, ull a, ull b) {
    asm("fma.rn.f32x2 %0, %1, %2, %0;" : "+l"(acc) : "l"(a), "l"(b));
}
__device__ __forceinline__ float fast_sig(float x) {
    float e, r;
    asm("ex2.approx.ftz.f32 %0, %1;" : "=f"(e) : "f"(x * -1.4426950408889634f));
    asm("rcp.approx.ftz.f32 %0, %1;" : "=f"(r) : "f"(e + 1.0f));
    return r;
}
__device__ __forceinline__ float fast_tanh(float x) {
    return fmaf(2.0f, fast_sig(2.0f * x), -1.0f);
}

// v rows (per batch, per layer, double buffered), 52 floats each:
//   l=0   : [ x_t, h0_self(25), 0 x 26 ]
//   l=1..3: [ h_{l-1}(25), 0, h_l_self(25), 0 ]
// fc reads v[b][3] with weights only on [26..50].

__global__ void __launch_bounds__(NTHR, 2) lstm_kernel(
    const float* __restrict__ x,
    const float* __restrict__ Wih1, const float* __restrict__ Whh1,
    const float* __restrict__ bih1, const float* __restrict__ bhh1,
    const float* __restrict__ Wih2, const float* __restrict__ Whh2,
    const float* __restrict__ bih2, const float* __restrict__ bhh2,
    const float* __restrict__ Wih3, const float* __restrict__ Whh3,
    const float* __restrict__ bih3, const float* __restrict__ bhh3,
    const float* __restrict__ Wih4, const float* __restrict__ Whh4,
    const float* __restrict__ bih4, const float* __restrict__ bhh4,
    const float* __restrict__ Wfc, const float* __restrict__ bfc,
    float* __restrict__ out, int write_states)
{
    __shared__ __align__(16) float v[BPB][4][2][52];

    const int tid = threadIdx.x;
    const int gb0 = blockIdx.x * BPB;        // batch elements gb0, gb0+1
    const int gb1 = gb0 + 1;

    // ---- role decode ----
    const bool isTask   = tid < 200;
    const bool isFc     = (tid == 200);
    const bool isStager = (tid == 201);
    int l, u, p;
    if (isTask) { l = tid / 50; int r = tid - l * 50; u = r >> 1; p = r & 1; }
    else        { l = 3; u = 0; p = tid & 1; }

    // ---- zero v buffers ----
    for (int i = tid; i < BPB * 4 * 2 * 52; i += NTHR) ((float*)v)[i] = 0.f;

    // ---- load this thread's 2 gate rows into registers (fused 52-wide) ----
    ull W0x[13], W0y[13], W1x[13], W1y[13];
    float bias0 = 0.f, bias1 = 0.f;
    {
        const float* WihL[4] = {Wih1, Wih2, Wih3, Wih4};
        const float* WhhL[4] = {Whh1, Whh2, Whh3, Whh4};
        const float* bihL[4] = {bih1, bih2, bih3, bih4};
        const float* bhhL[4] = {bhh1, bhh2, bhh3, bhh4};

        const float* pa0 = Wih1; const float* pb0 = Wih1;
        const float* pa1 = Wih1; const float* pb1 = Wih1;
        int aLo = 1, aHi = 0, bLo = 1, bHi = 0;   // empty by default

        if (isTask) {
            // gate order (i,f,g,o): p=0 -> rows {u, 25+u}; p=1 -> {50+u, 75+u}
            int row0 = p * 50 + u;
            int row1 = row0 + 25;
            if (l == 0) {
                pa0 = Wih1 + row0;        pa1 = Wih1 + row1;
                aLo = 0; aHi = 1;
                pb0 = Whh1 + row0 * 25;   pb1 = Whh1 + row1 * 25;
                bLo = 1; bHi = 26;
            } else {
                pa0 = WihL[l] + row0 * 25; pa1 = WihL[l] + row1 * 25;
                aLo = 0; aHi = 25;
                pb0 = WhhL[l] + row0 * 25; pb1 = WhhL[l] + row1 * 25;
                bLo = 26; bHi = 51;
            }
            bias0 = bihL[l][row0] + bhhL[l][row0];
            bias1 = bihL[l][row1] + bhhL[l][row1];
        } else if (isFc) {
            pb0 = Wfc; bLo = 26; bHi = 51;   // dot with h3 slot of v[b][3]
            bias0 = bfc[0];
        }

#pragma unroll
        for (int ch = 0; ch < 13; ++ch) {
            float f0[4], f1[4];
#pragma unroll
            for (int j = 0; j < 4; ++j) {
                int k = ch * 4 + j;
                float a = 0.f, b = 0.f;
                if (k >= aLo && k < aHi) { a = pa0[k - aLo]; b = pa1[k - aLo]; }
                if (k >= bLo && k < bHi) { a = pb0[k - bLo]; b = pb1[k - bLo]; }
                f0[j] = a; f1[j] = b;
            }
            W0x[ch] = pack2(f0[0], f0[1]); W0y[ch] = pack2(f0[2], f0[3]);
            W1x[ch] = pack2(f1[0], f1[1]); W1y[ch] = pack2(f1[2], f1[3]);
        }
    }

    // ---- stage x(0), prefetch x(1) for both batches ----
    float xr0 = 0.f, xr1 = 0.f;
    if (isStager) {
        v[0][0][0][0] = x[gb0];
        v[1][0][0][0] = x[gb1];
        xr0 = x[(size_t)NB + gb0];
        xr1 = x[(size_t)NB + gb1];
    }
    __syncthreads();

    float c[BPB], hreg[BPB];
#pragma unroll
    for (int b = 0; b < BPB; ++b) { c[b] = 0.f; hreg[b] = 0.f; }

    const float kmul = p ? 2.f : 1.f;     // tanh via 2*sig(2x)-1 on odd lanes
    const float kadd = p ? -1.f : 0.f;
    int par = l & 1;                      // = (T - l) & 1 when active
    const int selfIdx = (l == 0) ? (1 + u) : (26 + u);

    for (int T = 0; T < NTICKS; ++T) {
        // ---- dual-gate dot products for both batches (independent chains) ----
        float s0[BPB], s1[BPB];
#pragma unroll
        for (int b = 0; b < BPB; ++b) {
            ull A0 = pack2(bias0, 0.f), B0 = 0ull;
            ull A1 = pack2(bias1, 0.f), B1 = 0ull;
            const ulonglong2* V = (const ulonglong2*)v[b][l][par];
#pragma unroll
            for (int ch = 0; ch < 13; ++ch) {
                ulonglong2 hv = V[ch];
                fma2(A0, W0x[ch], hv.x); fma2(B0, W0y[ch], hv.y);
                fma2(A1, W1x[ch], hv.x); fma2(B1, W1y[ch], hv.y);
            }
            s0[b] = hsum2(A0) + hsum2(B0);
            s1[b] = hsum2(A1) + hsum2(B1);
        }

        // ---- special roles (warp 6) ----
        if (isFc) {
            int t = T - 4;                 // y(t) = h4(t)@Wfc + bfc
            if (t >= 0) {
                out[(size_t)t * NB + gb0] = s0[0];
                out[(size_t)t * NB + gb1] = s0[1];
            }
        }
        if (isStager) {
            int nb = (T + 1) & 1;
            v[0][0][nb][0] = xr0;          // x(T+1) for layer0's next tick
            v[1][0][nb][0] = xr1;
            int t2 = (T + 2 < Tlen) ? T + 2 : Tlen - 1;
            xr0 = x[(size_t)t2 * NB + gb0];
            xr1 = x[(size_t)t2 * NB + gb1];
        }

        // ---- activations + pair exchange + state update, per batch ----
        const bool act = isTask && (T >= l) && (T - l < Tlen);
#pragma unroll
        for (int b = 0; b < BPB; ++b) {
            float u0 = fast_sig(kmul * s0[b]);
            float a0 = fmaf(kmul, u0, kadd);   // p=0: sig  p=1: tanh
            float a1 = fast_sig(s1[b]);
            float x0 = __shfl_xor_sync(0xFFFFFFFFu, a0, 1);
            float x1 = __shfl_xor_sync(0xFFFFFFFFu, a1, 1);
            float si = p ? x0 : a0;
            float sf = p ? x1 : a1;
            float tg = p ? a0 : x0;
            float so = p ? a1 : x1;
            if (act) {
                c[b] = fmaf(sf, c[b], si * tg);    // both lanes identical c
                hreg[b] = so * fast_tanh(c[b]);
                if (p == 0)      v[b][l][par ^ 1][selfIdx] = hreg[b];
                else if (l < 3)  v[b][l + 1][par][u]       = hreg[b];
            }
        }
        par ^= 1;
        __syncthreads();
    }

    // ---- final states (h1,c1,h2,c2,h3,c3,h4,c4), each [4096,25] ----
    if (write_states && isTask && p == 0) {
        size_t base = (size_t)Tlen * NB;
        const size_t S = (size_t)NB * 25;
#pragma unroll
        for (int b = 0; b < BPB; ++b) {
            size_t idx = (size_t)(gb0 + b) * 25 + u;
            out[base + (size_t)(2 * l) * S + idx]     = hreg[b];
            out[base + (size_t)(2 * l + 1) * S + idx] = c[b];
        }
    }
}

extern "C" void kernel_launch(void* const* d_in, const int* in_sizes, int n_in,
                              void* d_out, int out_size) {
    (void)n_in; (void)in_sizes;
    const float* x    = (const float*)d_in[0];
    const float* Wih1 = (const float*)d_in[1];
    const float* Whh1 = (const float*)d_in[2];
    const float* bih1 = (const float*)d_in[3];
    const float* bhh1 = (const float*)d_in[4];
    const float* Wih2 = (const float*)d_in[5];
    const float* Whh2 = (const float*)d_in[6];
    const float* bih2 = (const float*)d_in[7];
    const float* bhh2 = (const float*)d_in[8];
    const float* Wih3 = (const float*)d_in[9];
    const float* Whh3 = (const float*)d_in[10];
    const float* bih3 = (const float*)d_in[11];
    const float* bhh3 = (const float*)d_in[12];
    const float* Wih4 = (const float*)d_in[13];
    const float* Whh4 = (const float*)d_in[14];
    const float* bih4 = (const float*)d_in[15];
    const float* bhh4 = (const float*)d_in[16];
    const float* Wfc  = (const float*)d_in[17];
    const float* bfc  = (const float*)d_in[18];

    int write_states = (out_size >= Tlen * NB + 8 * NB * 25) ? 1 : 0;

    lstm_kernel<<<NB / BPB, NTHR>>>(
        x, Wih1, Whh1, bih1, bhh1,
        Wih2, Whh2, bih2, bhh2,
        Wih3, Whh3, bih3, bhh3,
        Wih4, Whh4, bih4, bhh4,
        Wfc, bfc, (float*)d_out, write_states);
}

// round 6
// speedup vs baseline: 1.4480x; 1.1864x over previous
#include <cuda_runtime.h>
#include <cstdint>
#include <cstddef>

typedef unsigned long long ull;

#define Tlen 512
#define NB   4096
#define NTHR 256   // 8 warps; warp w owns units [3w .. 3w+2], warp 7 also unit 24

// ---- shared memory layout (float offsets), all 16B-aligned ----
#define W0_OFF    0                    // 100 rows x 28  = 2800  : L1 fused [Wih1|Whh1|pad2]
#define W123_OFF  2800                 // 3 x 100 x 52   = 15600 : L2-4 fused [Wih|0|Whh|0]
#define BIAS_OFF  (W123_OFF + 15600)   // 18400 : [4 layer][25 unit][4 gate] fused bih+bhh
#define WFC_OFF   (BIAS_OFF + 400)     // 18800 : 52-float fc row (W_fc at [26..50])
#define V0_OFF    (WFC_OFF + 52)       // 18852 : [2 buf][32 lane][28]  L1 v-rows
#define V123_OFF  (V0_OFF + 1792)      // 20644 : [3 layer][2 buf][32][52]
#define SMEM_FLOATS (V123_OFF + 9984)  // 30628 floats = 122512 bytes

__device__ __forceinline__ ull pack2(float lo, float hi) {
    return (ull)__float_as_uint(lo) | ((ull)__float_as_uint(hi) << 32);
}
__device__ __forceinline__ float hsum2(ull v) {
    float lo = __uint_as_float((unsigned)v);
    float hi = __uint_as_float((unsigned)(v >> 32));
    return lo + hi;
}
__device__ __forceinline__ void fma2(ull& acc, ull a, ull b) {
    asm("fma.rn.f32x2 %0, %1, %2, %0;" : "+l"(acc) : "l"(a), "l"(b));
}
__device__ __forceinline__ float fast_sig(float x) {
    float e, r;
    asm("ex2.approx.ftz.f32 %0, %1;" : "=f"(e) : "f"(x * -1.4426950408889634f));
    asm("rcp.approx.ftz.f32 %0, %1;" : "=f"(r) : "f"(e + 1.0f));
    return r;
}
__device__ __forceinline__ float fast_tanh(float x) {
    return fmaf(2.0f, fast_sig(2.0f * x), -1.0f);
}

// 4-gate dot products for one unit, v-row already in registers.
template<int NCH>
__device__ __forceinline__ void gates4reg(const ulonglong2* __restrict__ V,
    const float* __restrict__ w0, const float* __restrict__ w1,
    const float* __restrict__ w2, const float* __restrict__ w3,
    float b0, float b1, float b2, float b3,
    float& s0, float& s1, float& s2, float& s3)
{
    ull A0 = pack2(b0, 0.f), B0 = 0ull;
    ull A1 = pack2(b1, 0.f), B1 = 0ull;
    ull A2 = pack2(b2, 0.f), B2 = 0ull;
    ull A3 = pack2(b3, 0.f), B3 = 0ull;
    const ulonglong2* W0 = (const ulonglong2*)w0;
    const ulonglong2* W1 = (const ulonglong2*)w1;
    const ulonglong2* W2 = (const ulonglong2*)w2;
    const ulonglong2* W3 = (const ulonglong2*)w3;
#pragma unroll
    for (int ch = 0; ch < NCH; ++ch) {
        ulonglong2 w;
        w = W0[ch]; fma2(A0, w.x, V[ch].x); fma2(B0, w.y, V[ch].y);
        w = W1[ch]; fma2(A1, w.x, V[ch].x); fma2(B1, w.y, V[ch].y);
        w = W2[ch]; fma2(A2, w.x, V[ch].x); fma2(B2, w.y, V[ch].y);
        w = W3[ch]; fma2(A3, w.x, V[ch].x); fma2(B3, w.y, V[ch].y);
    }
    s0 = hsum2(A0) + hsum2(B0);
    s1 = hsum2(A1) + hsum2(B1);
    s2 = hsum2(A2) + hsum2(B2);
    s3 = hsum2(A3) + hsum2(B3);
}

__global__ void __launch_bounds__(NTHR) lstm_kernel(
    const float* __restrict__ x,
    const float* __restrict__ Wih1, const float* __restrict__ Whh1,
    const float* __restrict__ bih1, const float* __restrict__ bhh1,
    const float* __restrict__ Wih2, const float* __restrict__ Whh2,
    const float* __restrict__ bih2, const float* __restrict__ bhh2,
    const float* __restrict__ Wih3, const float* __restrict__ Whh3,
    const float* __restrict__ bih3, const float* __restrict__ bhh3,
    const float* __restrict__ Wih4, const float* __restrict__ Whh4,
    const float* __restrict__ bih4, const float* __restrict__ bhh4,
    const float* __restrict__ Wfc, const float* __restrict__ bfc,
    float* __restrict__ out, int write_states)
{
    extern __shared__ float smem[];
    const int tid = threadIdx.x;

    // ---- stage fused weights (row layouts identical to the passing R3 kernel) ----
    for (int i = tid; i < 2800; i += NTHR) {
        int g = i / 28, p = i - g * 28;
        float v = 0.f;
        if (p == 0)      v = Wih1[g];
        else if (p < 26) v = Whh1[g * 25 + p - 1];
        smem[W0_OFF + i] = v;
    }
    {
        const float* WihL[3] = {Wih2, Wih3, Wih4};
        const float* WhhL[3] = {Whh2, Whh3, Whh4};
        for (int i = tid; i < 15600; i += NTHR) {
            int l = i / 5200; int r = i - l * 5200;
            int g = r / 52,   p = r - g * 52;
            float v = 0.f;
            if (p < 25)                 v = WihL[l][g * 25 + p];
            else if (p >= 26 && p < 51) v = WhhL[l][g * 25 + p - 26];
            smem[W123_OFF + i] = v;
        }
        const float* bi[4] = {bih1, bih2, bih3, bih4};
        const float* bh[4] = {bhh1, bhh2, bhh3, bhh4};
        // bias as [layer][unit][gate] so one float4 covers a unit's 4 gates
        for (int i = tid; i < 400; i += NTHR) {
            int l = i / 100, r = i - l * 100, u = r >> 2, j = r & 3;
            smem[BIAS_OFF + i] = bi[l][j * 25 + u] + bh[l][j * 25 + u];
        }
    }
    for (int i = tid; i < 52; i += NTHR)
        smem[WFC_OFF + i] = (i >= 26 && i < 51) ? Wfc[i - 26] : 0.f;
    for (int i = tid; i < 1792 + 9984; i += NTHR) smem[V0_OFF + i] = 0.f;
    __syncthreads();

    const int lane  = tid & 31;
    const int wid   = tid >> 5;
    const int first = wid * 3;                  // owned units: first .. first+nu-1
    const int nu    = 3 + (wid == 7);           // warp 7 also owns unit 24
    const int gb    = (blockIdx.x << 5) + lane; // global batch element

    float xreg = 0.f, bfc_reg = 0.f;
    if (wid == 0) {
        smem[V0_OFF + lane * 28 + 0] = x[gb];   // x_0 -> buffer 0
        xreg = x[(size_t)NB + gb];              // prefetch x_1
    }
    if (wid == 1) bfc_reg = bfc[0];
    __syncthreads();

    float c[16];                                 // c[layer*4 + slot]
#pragma unroll
    for (int i = 0; i < 16; ++i) c[i] = 0.f;

    float* v0r = smem + V0_OFF   + lane * 28;    // + buf*896
    float* v1r = smem + V123_OFF + lane * 52;    // + buf*1664
    float* v2r = v1r + 3328;
    float* v3r = v2r + 3328;
    const float* biasS = smem + BIAS_OFF;
    const float* wfc   = smem + WFC_OFF;

    for (int t = 0; t < Tlen; ++t) {
        const int cur = t & 1, nxt = cur ^ 1;
        float* v0c = v0r + cur * 896;  float* v0n = v0r + nxt * 896;
        float* v1c = v1r + cur * 1664; float* v1n = v1r + nxt * 1664;
        float* v2c = v2r + cur * 1664; float* v2n = v2r + nxt * 1664;
        float* v3c = v3r + cur * 1664; float* v3n = v3r + nxt * 1664;

        // ---------- phase 1: layer 1 (+ stager, + fc one step behind) ----------
        if (wid == 0) {
            v0n[0] = xreg;                       // x_{t+1}
            int t2 = (t + 2 < Tlen) ? t + 2 : Tlen - 1;
            xreg = x[(size_t)t2 * NB + gb];
        }
        if (wid == 1 && t > 0) {                 // y(t-1) = h4(t-1)@Wfc + bfc
            const ulonglong2* V3 = (const ulonglong2*)v3c;
            const ulonglong2* WF = (const ulonglong2*)wfc;
            ull A = pack2(bfc_reg, 0.f), B = 0ull;
#pragma unroll
            for (int ch = 6; ch < 13; ++ch) {    // only [24..51]; wfc zero off [26..50]
                ulonglong2 hv = V3[ch]; ulonglong2 w = WF[ch];
                fma2(A, w.x, hv.x); fma2(B, w.y, hv.y);
            }
            out[(size_t)(t - 1) * NB + gb] = hsum2(A) + hsum2(B);
        }
        {
            ulonglong2 V[7];
#pragma unroll
            for (int ch = 0; ch < 7; ++ch) V[ch] = ((const ulonglong2*)v0c)[ch];
#pragma unroll
            for (int k = 0; k < 4; ++k) if (k < nu) {
                const int u = first + k;
                const float* wr = smem + W0_OFF + u * 28;
                float4 bb = *(const float4*)(biasS + u * 4);
                float s0, s1, s2, s3;
                gates4reg<7>(V, wr, wr + 700, wr + 1400, wr + 2100,
                             bb.x, bb.y, bb.z, bb.w, s0, s1, s2, s3);
                float fi = fast_sig(s0), ff = fast_sig(s1);
                float fg = fast_tanh(s2), fo = fast_sig(s3);
                c[k] = fmaf(ff, c[k], fi * fg);
                float h = fo * fast_tanh(c[k]);
                v0n[1 + u] = h; v1c[u] = h;
            }
        }
        __syncthreads();

        // ---------- phases 2-4: layers 2-4 ----------
#define LAYER_PHASE(LI, VC, VNSELF, VCHILD)                                     \
        {                                                                       \
            ulonglong2 V[13];                                                   \
            _Pragma("unroll")                                                   \
            for (int ch = 0; ch < 13; ++ch) V[ch] = ((const ulonglong2*)(VC))[ch]; \
            _Pragma("unroll")                                                   \
            for (int k = 0; k < 4; ++k) if (k < nu) {                           \
                const int u = first + k;                                        \
                const float* wr = smem + W123_OFF + (LI - 1) * 5200 + u * 52;   \
                float4 bb = *(const float4*)(biasS + LI * 100 + u * 4);         \
                float s0, s1, s2, s3;                                           \
                gates4reg<13>(V, wr, wr + 1300, wr + 2600, wr + 3900,           \
                              bb.x, bb.y, bb.z, bb.w, s0, s1, s2, s3);          \
                float fi = fast_sig(s0), ff = fast_sig(s1);                     \
                float fg = fast_tanh(s2), fo = fast_sig(s3);                    \
                c[LI * 4 + k] = fmaf(ff, c[LI * 4 + k], fi * fg);               \
                float h = fo * fast_tanh(c[LI * 4 + k]);                        \
                (VNSELF)[26 + u] = h;                                           \
                if (VCHILD) ((float*)(VCHILD))[u] = h;                          \
            }                                                                   \
        }

        LAYER_PHASE(1, v1c, v1n, v2c)
        __syncthreads();
        LAYER_PHASE(2, v2c, v2n, v3c)
        __syncthreads();
        LAYER_PHASE(3, v3c, v3n, (float*)0)
        __syncthreads();
#undef LAYER_PHASE
    }

    // ---- final fc: h4(T-1) is in v3 buffer 0 (Tlen even) ----
    if (wid == 1) {
        const ulonglong2* V3 = (const ulonglong2*)v3r;   // buffer 0
        const ulonglong2* WF = (const ulonglong2*)wfc;
        ull A = pack2(bfc_reg, 0.f), B = 0ull;
#pragma unroll
        for (int ch = 6; ch < 13; ++ch) {
            ulonglong2 hv = V3[ch]; ulonglong2 w = WF[ch];
            fma2(A, w.x, hv.x); fma2(B, w.y, hv.y);
        }
        out[(size_t)(Tlen - 1) * NB + gb] = hsum2(A) + hsum2(B);
    }

    // ---- final states (h1,c1,h2,c2,h3,c3,h4,c4), each [4096,25] ----
    if (write_states) {
        size_t base = (size_t)Tlen * NB;
        const size_t S = (size_t)NB * 25;
#pragma unroll
        for (int k = 0; k < 4; ++k) if (k < nu) {
            const int u = first + k;
            size_t idx = (size_t)gb * 25 + u;
            float h1v = v0r[1 + u];          // buffer 0 holds final self h's
            float h2v = v1r[26 + u];
            float h3v = v2r[26 + u];
            float h4v = v3r[26 + u];
            out[base + 0 * S + idx] = h1v;  out[base + 1 * S + idx] = c[k];
            out[base + 2 * S + idx] = h2v;  out[base + 3 * S + idx] = c[4 + k];
            out[base + 4 * S + idx] = h3v;  out[base + 5 * S + idx] = c[8 + k];
            out[base + 6 * S + idx] = h4v;  out[base + 7 * S + idx] = c[12 + k];
        }
    }
}

extern "C" void kernel_launch(void* const* d_in, const int* in_sizes, int n_in,
                              void* d_out, int out_size) {
    (void)n_in; (void)in_sizes;
    const float* x    = (const float*)d_in[0];
    const float* Wih1 = (const float*)d_in[1];
    const float* Whh1 = (const float*)d_in[2];
    const float* bih1 = (const float*)d_in[3];
    const float* bhh1 = (const float*)d_in[4];
    const float* Wih2 = (const float*)d_in[5];
    const float* Whh2 = (const float*)d_in[6];
    const float* bih2 = (const float*)d_in[7];
    const float* bhh2 = (const float*)d_in[8];
    const float* Wih3 = (const float*)d_in[9];
    const float* Whh3 = (const float*)d_in[10];
    const float* bih3 = (const float*)d_in[11];
    const float* bhh3 = (const float*)d_in[12];
    const float* Wih4 = (const float*)d_in[13];
    const float* Whh4 = (const float*)d_in[14];
    const float* bih4 = (const float*)d_in[15];
    const float* bhh4 = (const float*)d_in[16];
    const float* Wfc  = (const float*)d_in[17];
    const float* bfc  = (const float*)d_in[18];

    int smem_bytes = SMEM_FLOATS * (int)sizeof(float);
    static int configured = -1;
    if (configured != smem_bytes) {
        cudaFuncSetAttribute(lstm_kernel,
                             cudaFuncAttributeMaxDynamicSharedMemorySize, smem_bytes);
        configured = smem_bytes;
    }
    int write_states = (out_size >= Tlen * NB + 8 * NB * 25) ? 1 : 0;

    lstm_kernel<<<NB / 32, NTHR, smem_bytes>>>(
        x, Wih1, Whh1, bih1, bhh1,
        Wih2, Whh2, bih2, bhh2,
        Wih3, Whh3, bih3, bhh3,
        Wih4, Whh4, bih4, bhh4,
        Wfc, bfc, (float*)d_out, write_states);
}